// round 2
// baseline (speedup 1.0000x reference)
#include <cuda_runtime.h>
#include <cstdint>

#define T_STEPS 1000
#define BATCH   256
#define NIN     128
#define NHID    512
#define NOUT    128

#define NBLK 128
#define NTHR 256
#define BT 16      // batch rows per CTA
#define HT 64      // hidden cols per CTA

#define S_STRIDE4 130   // (512 + 8 pad) / 4
#define X_STRIDE4 34    // (128 + 8 pad) / 4

// shared-memory float offsets
#define OFF_WREC 0
#define OFF_WIN  (NHID*HT)                   // 32768
#define OFF_S    (OFF_WIN + NIN*HT)          // 40960
#define OFF_X    (OFF_S + BT*S_STRIDE4*4)    // 49280
#define SMEM_FLOATS (OFF_X + BT*X_STRIDE4*4) // 51456
#define SMEM_BYTES (SMEM_FLOATS*4)           // 205824 bytes

// s state ring (2 slots) — 1 MB, stays L2-resident
__device__ float    g_s_ring[2*BATCH*NHID];
__device__ unsigned g_count = 0;
__device__ unsigned g_gen   = 0;

__device__ __forceinline__ void grid_barrier() {
  __syncthreads();
  if (threadIdx.x == 0) {
    unsigned my = *((volatile unsigned*)&g_gen);
    __threadfence();
    if (atomicAdd(&g_count, 1u) == (unsigned)(NBLK - 1)) {
      atomicExch(&g_count, 0u);
      __threadfence();
      atomicExch(&g_gen, my + 1u);
    } else {
      while (*((volatile unsigned*)&g_gen) == my) { __nanosleep(32); }
    }
    __threadfence();
  }
  __syncthreads();
}

__device__ __forceinline__ void fma4(float4& acc, float s, const float4& wv) {
  acc.x = fmaf(s, wv.x, acc.x);
  acc.y = fmaf(s, wv.y, acc.y);
  acc.z = fmaf(s, wv.z, acc.z);
  acc.w = fmaf(s, wv.w, acc.w);
}

__global__ void __launch_bounds__(NTHR, 1)
bnn_kernel(const float* __restrict__ x,     // [T, B, NIN]
           const float* __restrict__ W_in,  // [NHID, NIN]
           const float* __restrict__ b_in,  // [NHID]
           const float* __restrict__ W_rec, // [NHID, NHID]
           const float* __restrict__ W_out, // [NOUT, NHID]
           const float* __restrict__ b_out, // [NOUT]
           float* __restrict__ out)         // [T, B, NOUT]
{
  extern __shared__ float sm[];
  float* wrec = sm + OFF_WREC;   // [k=512][h=64]
  float* win  = sm + OFF_WIN;    // [k=128][h=64]
  float* ss   = sm + OFF_S;      // [b=16][520]  (padded)
  float* xs   = sm + OFF_X;      // [b=16][136]  (padded)

  const int tid   = threadIdx.x;
  const int blk   = blockIdx.x;
  const int btile = blk >> 3;            // 16 b-tiles
  const int htile = blk & 7;             // 8  h-tiles
  const int b0 = btile * BT;
  const int h0 = htile * HT;

  // ---- prologue: cache weight tiles in SMEM (once for all 1000 steps) ----
  for (int i = tid; i < HT*NHID; i += NTHR) {
    int hl = i >> 9, k = i & 511;
    wrec[k*HT + hl] = W_rec[(h0 + hl)*NHID + k];
  }
  for (int i = tid; i < HT*NIN; i += NTHR) {
    int hl = i >> 7, k = i & 127;
    win[k*HT + hl] = W_in[(h0 + hl)*NIN + k];
  }
  // zero ss (s[-1] = 0), stage x[0]
  for (int i = tid; i < BT*S_STRIDE4; i += NTHR)
    ((float4*)ss)[i] = make_float4(0.f, 0.f, 0.f, 0.f);
  for (int i = tid; i < BT*32; i += NTHR) {
    int r = i >> 5, c = i & 31;
    ((float4*)xs)[r*X_STRIDE4 + c] =
        ((const float4*)x)[((size_t)(b0 + r))*32 + c];   // t = 0
  }
  __syncthreads();

  // ---- per-thread mapping: warp = 4b x 8hg (contiguous 128B W reads) ----
  const int warp = tid >> 5;
  const int hg = ((warp & 1) << 3) | (tid & 7);          // 0..15
  const int bl = ((warp >> 1) << 2) | ((tid >> 3) & 3);  // 0..15

  const float4 bin = *((const float4*)(b_in + h0) + hg);

  // readout mapping: 16b x 16o per CTA, 1 output per thread
  const int ob = tid >> 4;
  const int o  = htile * 16 + (tid & 15);
  const float bo = b_out[o];
  const float4* wo = (const float4*)(W_out + (size_t)o * NHID);

  const float4* wr4 = (const float4*)wrec;  // [k][16]
  const float4* wi4 = (const float4*)win;   // [k][16]
  const float4* s4  = (const float4*)ss;
  const float4* x4  = (const float4*)xs;

  float4 v  = make_float4(0.f,0.f,0.f,0.f);
  float4 a0 = make_float4(0.f,0.f,0.f,0.f);
  float4 a1 = make_float4(0.f,0.f,0.f,0.f);
  float4 sp = make_float4(0.f,0.f,0.f,0.f);

  for (int t = 0; t < T_STEPS; ++t) {
    // ---- y = x @ W_in^T + s_prev @ W_rec^T ----
    float4 acca = make_float4(0.f,0.f,0.f,0.f);
    float4 accb = make_float4(0.f,0.f,0.f,0.f);
    #pragma unroll 4
    for (int k4 = 0; k4 < 128; ++k4) {
      float4 sv = s4[bl*S_STRIDE4 + k4];
      float4 w0 = wr4[(k4*4 + 0)*16 + hg];
      float4 w1 = wr4[(k4*4 + 1)*16 + hg];
      float4 w2 = wr4[(k4*4 + 2)*16 + hg];
      float4 w3 = wr4[(k4*4 + 3)*16 + hg];
      fma4(acca, sv.x, w0);
      fma4(accb, sv.y, w1);
      fma4(acca, sv.z, w2);
      fma4(accb, sv.w, w3);
    }
    #pragma unroll 4
    for (int k4 = 0; k4 < 32; ++k4) {
      float4 xv = x4[bl*X_STRIDE4 + k4];
      float4 w0 = wi4[(k4*4 + 0)*16 + hg];
      float4 w1 = wi4[(k4*4 + 1)*16 + hg];
      float4 w2 = wi4[(k4*4 + 2)*16 + hg];
      float4 w3 = wi4[(k4*4 + 3)*16 + hg];
      fma4(acca, xv.x, w0);
      fma4(accb, xv.y, w1);
      fma4(acca, xv.z, w2);
      fma4(accb, xv.w, w3);
    }
    float4 acc;
    acc.x = acca.x + accb.x; acc.y = acca.y + accb.y;
    acc.z = acca.z + accb.z; acc.w = acca.w + accb.w;

    // ---- GLIFR neuron update (fp32, per component) ----
    #define UPD(i) { \
      float y  = 0.5f*(acc.i + bin.i); \
      a0.i = fmaf(a0.i,  0.85f, -0.05f*sp.i); \
      a1.i = fmaf(a1.i, -0.5f,  -0.05f*sp.i); \
      float it = y + a0.i + a1.i + 700.0f; \
      v.i  = v.i*0.99f*(1.0f - 0.05f*sp.i) + 0.00101953125f*it; \
      sp.i = 20.0f / (1.0f + __expf(-v.i*0.02f)); }
    UPD(x); UPD(y); UPD(z); UPD(w);
    #undef UPD

    // publish s[t] to L2-resident ring
    {
      float4* sdst = (float4*)g_s_ring +
          ((size_t)(t & 1)*BATCH*NHID + (size_t)(b0 + bl)*NHID + h0)/4 + hg;
      *sdst = sp;
    }
    __threadfence();
    grid_barrier();

    // ---- restage s[t] (all 512 h for our 16 b), stage x[t+1] ----
    for (int i = tid; i < BT*128; i += NTHR) {
      int r = i >> 7, c = i & 127;
      ((float4*)ss)[r*S_STRIDE4 + c] = ((const float4*)g_s_ring)
          [((size_t)(t & 1)*BATCH + b0 + r)*128 + c];
    }
    {
      int tn = (t + 1 < T_STEPS) ? t + 1 : t;
      for (int i = tid; i < BT*32; i += NTHR) {
        int r = i >> 5, c = i & 31;
        ((float4*)xs)[r*X_STRIDE4 + c] =
            ((const float4*)x)[((size_t)tn*BATCH + b0 + r)*32 + c];
      }
    }
    __syncthreads();

    // ---- readout: out[t] = s[t] @ W_out^T + b_out ----
    {
      float oa = 0.f, obacc = 0.f;
      #pragma unroll 4
      for (int k4 = 0; k4 < 128; k4 += 2) {
        float4 sv0 = s4[ob*S_STRIDE4 + k4];
        float4 wv0 = __ldg(wo + k4);
        float4 sv1 = s4[ob*S_STRIDE4 + k4 + 1];
        float4 wv1 = __ldg(wo + k4 + 1);
        oa    = fmaf(sv0.x, wv0.x, fmaf(sv0.y, wv0.y,
                fmaf(sv0.z, wv0.z, fmaf(sv0.w, wv0.w, oa))));
        obacc = fmaf(sv1.x, wv1.x, fmaf(sv1.y, wv1.y,
                fmaf(sv1.z, wv1.z, fmaf(sv1.w, wv1.w, obacc))));
      }
      out[(size_t)t*BATCH*NOUT + (size_t)(b0 + ob)*NOUT + o] = oa + obacc + bo;
    }
    // next iteration's ss overwrite is gated by the next grid_barrier's
    // __syncthreads, so the readout reads above are safe.
  }
}

extern "C" void kernel_launch(void* const* d_in, const int* in_sizes, int n_in,
                              void* d_out, int out_size) {
  const float* x     = (const float*)d_in[0];
  const float* W_in  = (const float*)d_in[1];
  const float* b_in  = (const float*)d_in[2];
  const float* W_rec = (const float*)d_in[3];
  const float* W_out = (const float*)d_in[4];
  const float* b_out = (const float*)d_in[5];
  float* out = (float*)d_out;

  cudaFuncSetAttribute(bnn_kernel,
                       cudaFuncAttributeMaxDynamicSharedMemorySize, SMEM_BYTES);
  bnn_kernel<<<NBLK, NTHR, SMEM_BYTES>>>(x, W_in, b_in, W_rec, W_out, b_out, out);
}

// round 3
// speedup vs baseline: 1.0586x; 1.0586x over previous
#include <cuda_runtime.h>
#include <cstdint>

#define T_STEPS 1000
#define BATCH   256
#define NIN     128
#define NHID    512
#define NOUT    128

#define NBLK 128
#define NTHR 512
#define BT 16      // batch rows per CTA
#define HT 64      // hidden cols per CTA

#define S_STRIDE4 129   // float4 stride for s rows (516 floats -> 4-bank shift/row)
#define X_STRIDE4 33    // float4 stride for x rows (132 floats -> 4-bank shift/row)

// shared-memory float offsets
#define OFF_WREC 0
#define OFF_WIN  (NHID*HT)                   // 32768
#define OFF_S    (OFF_WIN + NIN*HT)          // 40960
#define OFF_X    (OFF_S + BT*S_STRIDE4*4)    // 49216
#define SMEM_FLOATS (OFF_X + BT*X_STRIDE4*4) // 51328
#define SMEM_BYTES (SMEM_FLOATS*4)           // 205312 bytes

// s state ring (2 slots) — 1 MB, stays L2-resident (.cg accessed only)
__device__ float    g_s_ring[2*BATCH*NHID];
__device__ unsigned g_count = 0;
__device__ unsigned g_gen   = 0;

typedef unsigned long long u64;

__device__ __forceinline__ void ffma2(u64& d, u64 a, u64 b) {
  asm("fma.rn.f32x2 %0, %1, %2, %0;" : "+l"(d) : "l"(a), "l"(b));
}
__device__ __forceinline__ u64 bcast2(float s) {
  u64 r; asm("mov.b64 %0, {%1, %1};" : "=l"(r) : "f"(s)); return r;
}
__device__ __forceinline__ float2 unpack2(u64 p) {
  float2 f; asm("mov.b64 {%0, %1}, %2;" : "=f"(f.x), "=f"(f.y) : "l"(p)); return f;
}

// generation-based grid barrier; acq_rel fences (no sc fence -> cheaper),
// all cross-CTA payload goes through L2 (.cg), so no L1 invalidation needed.
__device__ __forceinline__ void grid_barrier() {
  __syncthreads();
  if (threadIdx.x == 0) {
    asm volatile("fence.acq_rel.gpu;" ::: "memory");   // release our s stores
    unsigned my = *((volatile unsigned*)&g_gen);
    if (atomicAdd(&g_count, 1u) == (unsigned)(NBLK - 1)) {
      atomicExch(&g_count, 0u);
      asm volatile("fence.acq_rel.gpu;" ::: "memory");
      atomicExch(&g_gen, my + 1u);
    } else {
      while (*((volatile unsigned*)&g_gen) == my) { }
    }
    asm volatile("fence.acq_rel.gpu;" ::: "memory");   // acquire
  }
  __syncthreads();
}

__global__ void __launch_bounds__(NTHR, 1)
bnn_kernel(const float* __restrict__ x,     // [T, B, NIN]
           const float* __restrict__ W_in,  // [NHID, NIN]
           const float* __restrict__ b_in,  // [NHID]
           const float* __restrict__ W_rec, // [NHID, NHID]
           const float* __restrict__ W_out, // [NOUT, NHID]
           const float* __restrict__ b_out, // [NOUT]
           float* __restrict__ out)         // [T, B, NOUT]
{
  extern __shared__ float sm[];
  float* wrec = sm + OFF_WREC;   // [k=512][h=64]
  float* win  = sm + OFF_WIN;    // [k=128][h=64]
  float* ss   = sm + OFF_S;      // [b=16][516]  (padded)
  float* xs   = sm + OFF_X;      // [b=16][132]  (padded)

  const int tid   = threadIdx.x;
  const int blk   = blockIdx.x;
  const int btile = blk >> 3;            // 16 b-tiles
  const int htile = blk & 7;             // 8  h-tiles
  const int b0 = btile * BT;
  const int h0 = htile * HT;

  // ---- prologue: cache weight tiles in SMEM (once for all 1000 steps) ----
  for (int i = tid; i < HT*NHID; i += NTHR) {
    int hl = i >> 9, k = i & 511;
    wrec[k*HT + hl] = W_rec[(h0 + hl)*NHID + k];
  }
  for (int i = tid; i < HT*NIN; i += NTHR) {
    int hl = i >> 7, k = i & 127;
    win[k*HT + hl] = W_in[(h0 + hl)*NIN + k];
  }
  // zero ss (s[-1] = 0), stage x[0]
  for (int i = tid; i < BT*S_STRIDE4; i += NTHR)
    ((float4*)ss)[i] = make_float4(0.f, 0.f, 0.f, 0.f);
  for (int i = tid; i < BT*32; i += NTHR) {
    int r = i >> 5, c = i & 31;
    ((float4*)xs)[r*X_STRIDE4 + c] =
        ((const float4*)x)[((size_t)(b0 + r))*32 + c];   // t = 0
  }
  __syncthreads();

  // ---- per-thread mapping: warp = 4hg x 4bl x 2kh (in-warp k-split) ----
  const int warp = tid >> 5;
  const int lane = tid & 31;
  const int hg = ((warp & 3) << 2) | (lane & 3);            // 0..15 (4 floats each)
  const int bl = (((warp >> 2) & 3) << 2) | ((lane >> 2) & 3); // 0..15
  const int kh = lane >> 4;                                 // 0/1 (interleaved k4)

  const float4 bin = *((const float4*)(b_in + h0) + hg);

  // readout mapping: warp = batch row, lanes 0..15 = outputs, lane bit4 = k half
  const int ob = warp;                       // 0..15
  const int o  = htile * 16 + (lane & 15);   // 0..127
  const float bo = b_out[o];
  const float4* wo = (const float4*)(W_out + (size_t)o * NHID);

  const ulonglong2* wr2 = (const ulonglong2*)wrec;  // [k][16] float4 == ull2
  const ulonglong2* wi2 = (const ulonglong2*)win;
  const float4* s4 = (const float4*)ss;
  const float4* x4 = (const float4*)xs;

  float4 v  = make_float4(0.f,0.f,0.f,0.f);
  float4 a0 = make_float4(0.f,0.f,0.f,0.f);
  float4 a1 = make_float4(0.f,0.f,0.f,0.f);
  float4 sp = make_float4(0.f,0.f,0.f,0.f);

  for (int t = 0; t < T_STEPS; ++t) {
    // ---- y-partials: this lane covers k4 = 2*i + kh ----
    u64 aA0 = 0, aA1 = 0, aB0 = 0, aB1 = 0;  // [h0h1|h2h3] x (even j | odd j)

    #pragma unroll 4
    for (int i = 0; i < 64; ++i) {           // recurrent: 128 k4 total, half each
      int k4 = 2*i + kh;
      float4 sv = s4[bl*S_STRIDE4 + k4];
      ulonglong2 w0 = wr2[(k4*4 + 0)*16 + hg];
      ulonglong2 w1 = wr2[(k4*4 + 1)*16 + hg];
      ulonglong2 w2 = wr2[(k4*4 + 2)*16 + hg];
      ulonglong2 w3 = wr2[(k4*4 + 3)*16 + hg];
      u64 sx = bcast2(sv.x), sy = bcast2(sv.y);
      u64 sz = bcast2(sv.z), sw = bcast2(sv.w);
      ffma2(aA0, sx, w0.x); ffma2(aA1, sx, w0.y);
      ffma2(aB0, sy, w1.x); ffma2(aB1, sy, w1.y);
      ffma2(aA0, sz, w2.x); ffma2(aA1, sz, w2.y);
      ffma2(aB0, sw, w3.x); ffma2(aB1, sw, w3.y);
    }
    #pragma unroll 4
    for (int i = 0; i < 16; ++i) {           // input: 32 k4 total, half each
      int k4 = 2*i + kh;
      float4 xv = x4[bl*X_STRIDE4 + k4];
      ulonglong2 w0 = wi2[(k4*4 + 0)*16 + hg];
      ulonglong2 w1 = wi2[(k4*4 + 1)*16 + hg];
      ulonglong2 w2 = wi2[(k4*4 + 2)*16 + hg];
      ulonglong2 w3 = wi2[(k4*4 + 3)*16 + hg];
      u64 sx = bcast2(xv.x), sy = bcast2(xv.y);
      u64 sz = bcast2(xv.z), sw = bcast2(xv.w);
      ffma2(aA0, sx, w0.x); ffma2(aA1, sx, w0.y);
      ffma2(aB0, sy, w1.x); ffma2(aB1, sy, w1.y);
      ffma2(aA0, sz, w2.x); ffma2(aA1, sz, w2.y);
      ffma2(aB0, sw, w3.x); ffma2(aB1, sw, w3.y);
    }
    // combine halves within lane, then across kh via shfl
    float2 p0 = unpack2(aA0), p1 = unpack2(aA1);
    float2 q0 = unpack2(aB0), q1 = unpack2(aB1);
    float4 acc;
    acc.x = p0.x + q0.x; acc.y = p0.y + q0.y;
    acc.z = p1.x + q1.x; acc.w = p1.y + q1.y;
    acc.x += __shfl_xor_sync(0xffffffffu, acc.x, 16);
    acc.y += __shfl_xor_sync(0xffffffffu, acc.y, 16);
    acc.z += __shfl_xor_sync(0xffffffffu, acc.z, 16);
    acc.w += __shfl_xor_sync(0xffffffffu, acc.w, 16);

    // ---- GLIFR neuron update (both kh lanes compute identically) ----
    #define UPD(i) { \
      float y  = 0.5f*(acc.i + bin.i); \
      a0.i = fmaf(a0.i,  0.85f, -0.05f*sp.i); \
      a1.i = fmaf(a1.i, -0.5f,  -0.05f*sp.i); \
      float it = y + a0.i + a1.i + 700.0f; \
      v.i  = v.i*0.99f*(1.0f - 0.05f*sp.i) + 0.00101953125f*it; \
      sp.i = 20.0f / (1.0f + __expf(-v.i*0.02f)); }
    UPD(x); UPD(y); UPD(z); UPD(w);
    #undef UPD

    // publish s[t] to L2 ring (kh=0 lanes only), bypass L1
    if (kh == 0) {
      float4* sdst = (float4*)(g_s_ring + (size_t)(t & 1)*BATCH*NHID
                               + (size_t)(b0 + bl)*NHID + h0) + hg;
      __stcg(sdst, sp);
    }
    grid_barrier();

    // ---- restage s[t] (all 512 h for our 16 b) from L2, stage x[t+1] ----
    for (int i = tid; i < BT*128; i += NTHR) {
      int r = i >> 7, c = i & 127;
      ((float4*)ss)[r*S_STRIDE4 + c] = __ldcg(((const float4*)g_s_ring)
          + ((size_t)(t & 1)*BATCH + b0 + r)*128 + c);
    }
    {
      int tn = (t + 1 < T_STEPS) ? t + 1 : t;
      for (int i = tid; i < BT*32; i += NTHR) {
        int r = i >> 5, c = i & 31;
        ((float4*)xs)[r*X_STRIDE4 + c] =
            ((const float4*)x)[((size_t)tn*BATCH + b0 + r)*32 + c];
      }
    }
    __syncthreads();

    // ---- readout: out[t] = s[t] @ W_out^T + b_out (k split across lane bit4) ----
    {
      float oa = 0.f, obacc = 0.f;
      #pragma unroll 8
      for (int i = 0; i < 32; ++i) {
        int k4 = 4*i + 2*kh;   // halves take interleaved pairs of float4
        float4 sv0 = s4[ob*S_STRIDE4 + k4];
        float4 wv0 = __ldg(wo + k4);
        float4 sv1 = s4[ob*S_STRIDE4 + k4 + 1];
        float4 wv1 = __ldg(wo + k4 + 1);
        oa    = fmaf(sv0.x, wv0.x, fmaf(sv0.y, wv0.y,
                fmaf(sv0.z, wv0.z, fmaf(sv0.w, wv0.w, oa))));
        obacc = fmaf(sv1.x, wv1.x, fmaf(sv1.y, wv1.y,
                fmaf(sv1.z, wv1.z, fmaf(sv1.w, wv1.w, obacc))));
      }
      float r = oa + obacc;
      r += __shfl_xor_sync(0xffffffffu, r, 16);
      if (kh == 0)
        out[(size_t)t*BATCH*NOUT + (size_t)(b0 + ob)*NOUT + o] = r + bo;
    }
    // next iteration's ss/xs overwrite is gated by the next grid_barrier's
    // entry __syncthreads, so the reads above are safe.
  }
}

extern "C" void kernel_launch(void* const* d_in, const int* in_sizes, int n_in,
                              void* d_out, int out_size) {
  const float* x     = (const float*)d_in[0];
  const float* W_in  = (const float*)d_in[1];
  const float* b_in  = (const float*)d_in[2];
  const float* W_rec = (const float*)d_in[3];
  const float* W_out = (const float*)d_in[4];
  const float* b_out = (const float*)d_in[5];
  float* out = (float*)d_out;

  cudaFuncSetAttribute(bnn_kernel,
                       cudaFuncAttributeMaxDynamicSharedMemorySize, SMEM_BYTES);
  bnn_kernel<<<NBLK, NTHR, SMEM_BYTES>>>(x, W_in, b_in, W_rec, W_out, b_out, out);
}